// round 2
// baseline (speedup 1.0000x reference)
#include <cuda_runtime.h>

// CumulativeLayerNorm: B=8, K=8192, H=512, fp32 in/out.
// Single-pass fused kernel: per-row moments -> decoupled-lookback prefix scan
// over K (per batch) -> normalize, with the input tile held in registers.
// Input is read exactly once; output written exactly once (268 MB total).

#define Bb      8
#define Kk      8192
#define Hh      512
#define H4      (Hh / 4)      // 128 float4 per row
#define TILE_K  64            // rows per CTA
#define CHUNKS  (Kk / TILE_K) // 128 chunks per batch
#define NBLK    (Bb * CHUNKS) // 1024 CTAs
#define NTHR    512

// Lookback state (device globals: no allocation allowed).
// Separate aggregate / inclusive slots so a reader that saw the flag can never
// observe a torn/overwritten value (128-bit payloads can't be CAS'd).
__device__ double g_agg_s[NBLK];
__device__ double g_agg_ss[NBLK];
__device__ double g_inc_s[NBLK];
__device__ double g_inc_ss[NBLK];
__device__ int    g_flag[NBLK];   // 0 = invalid, 1 = aggregate ready, 2 = inclusive ready

__global__ void k_init_flags() {
    int i = blockIdx.x * blockDim.x + threadIdx.x;
    if (i < NBLK) g_flag[i] = 0;
}

__global__ __launch_bounds__(NTHR, 1)
void k_cumln(const float4* __restrict__ x4,
             const float4* __restrict__ gam4,
             const float4* __restrict__ bet4,
             float4* __restrict__ out4)
{
    __shared__ float4 sh_g[H4];
    __shared__ float4 sh_b[H4];
    __shared__ float  sh_rs[TILE_K];
    __shared__ float  sh_rss[TILE_K];
    __shared__ double sh_is[TILE_K];    // inclusive in-tile scan (sum)
    __shared__ double sh_iss[TILE_K];   // inclusive in-tile scan (sqsum)
    __shared__ float  sh_mean[TILE_K];
    __shared__ float  sh_istd[TILE_K];
    __shared__ double sh_ex[2];         // exclusive chunk prefix

    const int tid  = threadIdx.x;
    const int lane = tid & 31;
    const int warp = tid >> 5;          // 0..15
    const int idx  = blockIdx.x;
    const int b    = idx >> 7;          // idx / CHUNKS  (CHUNKS==128)
    const int c    = idx & (CHUNKS - 1);
    const int batch_start = b << 7;

    // Stage gamma/beta into smem (2 KB each).
    if (tid < H4) { sh_g[tid] = gam4[tid]; sh_b[tid] = bet4[tid]; }

    // ---- Load tile into registers (streaming, read-once) + per-row reduce ----
    // warp w owns rows [4w, 4w+4); per row each lane reads 4 coalesced float4.
    const int row0  = warp << 2;
    const int grow0 = b * Kk + c * TILE_K;   // global row of tile row 0
    float4 v[4][4];
#pragma unroll
    for (int j = 0; j < 4; ++j) {
        const int base = (grow0 + row0 + j) * H4;   // < 2^23, int ok
#pragma unroll
        for (int q = 0; q < 4; ++q)
            v[j][q] = __ldcs(&x4[base + lane + 32 * q]);
    }
#pragma unroll
    for (int j = 0; j < 4; ++j) {
        float s = 0.f, ss = 0.f;
#pragma unroll
        for (int q = 0; q < 4; ++q) {
            float4 t = v[j][q];
            s  += (t.x + t.y) + (t.z + t.w);
            ss += (t.x * t.x + t.y * t.y) + (t.z * t.z + t.w * t.w);
        }
#pragma unroll
        for (int o = 16; o; o >>= 1) {
            s  += __shfl_xor_sync(0xffffffffu, s,  o);
            ss += __shfl_xor_sync(0xffffffffu, ss, o);
        }
        if (lane == 0) { sh_rs[row0 + j] = s; sh_rss[row0 + j] = ss; }
    }
    __syncthreads();

    // ---- In-tile serial scan (fp64) + decoupled lookback (warp 0) ----
    if (warp == 0) {
        double agg_s = 0.0, agg_ss = 0.0;
        if (lane == 0) {
            double rs = 0.0, rss = 0.0;
            for (int r = 0; r < TILE_K; ++r) {
                rs  += (double)sh_rs[r];
                rss += (double)sh_rss[r];
                sh_is[r]  = rs;
                sh_iss[r] = rss;
            }
            agg_s = rs; agg_ss = rss;
            if (c == 0) {
                g_inc_s[idx]  = rs;
                g_inc_ss[idx] = rss;
                __threadfence();
                atomicExch(&g_flag[idx], 2);
            } else {
                g_agg_s[idx]  = rs;
                g_agg_ss[idx] = rss;
                __threadfence();
                atomicExch(&g_flag[idx], 1);
            }
        }
        __syncwarp();

        double ex_s = 0.0, ex_ss = 0.0;
        if (c != 0) {
            int cur = idx - 1;           // warp-parallel lookback, 32 preds/round
            for (;;) {
                const int p = cur - lane;
                int f = 3;               // sentinel: out of this batch's range
                if (p >= batch_start) {
                    const volatile int* fp = (const volatile int*)&g_flag[p];
                    f = *fp;
                    while (f == 0) { __nanosleep(64); f = *fp; }
                }
                __threadfence();         // acquire: order value reads after flag read
                double vs = 0.0, vss = 0.0;
                const unsigned done_mask = __ballot_sync(0xffffffffu, f >= 2);
                const int L = done_mask ? (__ffs(done_mask) - 1) : 32;
                if (lane < L)                 { vs = g_agg_s[p]; vss = g_agg_ss[p]; }
                else if (lane == L && f == 2) { vs = g_inc_s[p]; vss = g_inc_ss[p]; }
                // lane==L && f==3 (out-of-range sentinel) contributes 0
#pragma unroll
                for (int o = 16; o; o >>= 1) {
                    vs  += __shfl_xor_sync(0xffffffffu, vs,  o);
                    vss += __shfl_xor_sync(0xffffffffu, vss, o);
                }
                ex_s += vs; ex_ss += vss;
                if (done_mask) break;
                cur -= 32;
            }
            if (lane == 0) {
                g_inc_s[idx]  = ex_s + agg_s;
                g_inc_ss[idx] = ex_ss + agg_ss;
                __threadfence();
                atomicExch(&g_flag[idx], 2);
            }
        }
        if (lane == 0) { sh_ex[0] = ex_s; sh_ex[1] = ex_ss; }
    }
    __syncthreads();

    // ---- Per-row mean / inv_std ----
    if (tid < TILE_K) {
        const double ts  = sh_ex[0] + sh_is[tid];
        const double tss = sh_ex[1] + sh_iss[tid];
        const double cnt = (double)((long long)(c * TILE_K + tid + 1) * Hh);
        const double mean = ts / cnt;
        const double var  = tss / cnt - mean * mean;
        sh_mean[tid] = (float)mean;
        sh_istd[tid] = rsqrtf((float)var + 1e-8f);
    }
    __syncthreads();

    // ---- Normalize from registers and store (streaming, write-once) ----
#pragma unroll
    for (int j = 0; j < 4; ++j) {
        const float mean = sh_mean[row0 + j];
        const float istd = sh_istd[row0 + j];
        const int base = (grow0 + row0 + j) * H4;
#pragma unroll
        for (int q = 0; q < 4; ++q) {
            const int col = lane + 32 * q;
            const float4 g = sh_g[col];
            const float4 be = sh_b[col];
            const float4 t = v[j][q];
            float4 o;
            o.x = g.x * (t.x - mean) * istd + be.x;
            o.y = g.y * (t.y - mean) * istd + be.y;
            o.z = g.z * (t.z - mean) * istd + be.z;
            o.w = g.w * (t.w - mean) * istd + be.w;
            __stcs(&out4[base + col], o);
        }
    }
}

extern "C" void kernel_launch(void* const* d_in, const int* in_sizes, int n_in,
                              void* d_out, int out_size)
{
    const float4* x4   = (const float4*)d_in[0];  // inputs (B,K,H) fp32
    const float4* gam4 = (const float4*)d_in[1];  // gamma (1,H)
    const float4* bet4 = (const float4*)d_in[2];  // beta  (1,H)
    float4* out4 = (float4*)d_out;

    k_init_flags<<<(NBLK + 255) / 256, 256>>>();
    k_cumln<<<NBLK, NTHR>>>(x4, gam4, bet4, out4);
}

// round 5
// speedup vs baseline: 1.0440x; 1.0440x over previous
#include <cuda_runtime.h>

// CumulativeLayerNorm: B=8, K=8192, H=512, fp32 in/out.
// Single-pass fused: per-row moments -> decoupled-lookback prefix scan over K
// (per batch) -> normalize, tile held in registers. Input read once, output
// written once (268 MB total).
// R2 -> R5: TILE_K 64->16, 256 thr, 4 CTAs/SM so independent CTAs overlap the
// (memory-idle) scan/lookback phase with other CTAs' load/store phases.

#define Bb      8
#define Kk      8192
#define Hh      512
#define H4      (Hh / 4)      // 128 float4 per row
#define TILE_K  16            // rows per CTA
#define CHUNKS  (Kk / TILE_K) // 512 chunks per batch
#define NBLK    (Bb * CHUNKS) // 4096 CTAs
#define NTHR    256           // 8 warps; 2 rows per warp

// Lookback state (device globals: no allocation allowed).
// Separate aggregate / inclusive slots so a reader that saw the flag can never
// observe a torn/overwritten value (128-bit payloads can't be CAS'd).
__device__ double g_agg_s[NBLK];
__device__ double g_agg_ss[NBLK];
__device__ double g_inc_s[NBLK];
__device__ double g_inc_ss[NBLK];
__device__ int    g_flag[NBLK];   // 0 = invalid, 1 = aggregate ready, 2 = inclusive ready

__global__ void k_init_flags() {
    int i = blockIdx.x * blockDim.x + threadIdx.x;
    if (i < NBLK) g_flag[i] = 0;
}

__global__ __launch_bounds__(NTHR, 4)
void k_cumln(const float4* __restrict__ x4,
             const float4* __restrict__ gam4,
             const float4* __restrict__ bet4,
             float4* __restrict__ out4)
{
    __shared__ float4 sh_g[H4];
    __shared__ float4 sh_b[H4];
    __shared__ float  sh_rs[TILE_K];
    __shared__ float  sh_rss[TILE_K];
    __shared__ double sh_is[TILE_K];    // inclusive in-tile scan (sum)
    __shared__ double sh_iss[TILE_K];   // inclusive in-tile scan (sqsum)
    __shared__ float  sh_mean[TILE_K];
    __shared__ float  sh_istd[TILE_K];
    __shared__ double sh_ex[2];         // exclusive chunk prefix

    const int tid  = threadIdx.x;
    const int lane = tid & 31;
    const int warp = tid >> 5;          // 0..7
    const int idx  = blockIdx.x;
    const int b    = idx >> 9;          // idx / CHUNKS  (CHUNKS==512)
    const int c    = idx & (CHUNKS - 1);
    const int batch_start = b << 9;

    // Stage gamma/beta into smem (2 KB each); L2-resident after wave 1.
    if (tid < H4) { sh_g[tid] = gam4[tid]; sh_b[tid] = bet4[tid]; }

    // ---- Load tile into registers (streaming, read-once) + per-row reduce ----
    // warp w owns rows {2w, 2w+1}; per row each lane reads 4 coalesced float4.
    const int row0  = warp << 1;
    const int grow0 = b * Kk + c * TILE_K;   // global row of tile row 0
    float4 v[2][4];
#pragma unroll
    for (int j = 0; j < 2; ++j) {
        const int base = (grow0 + row0 + j) * H4;   // < 2^23, int ok
#pragma unroll
        for (int q = 0; q < 4; ++q)
            v[j][q] = __ldcs(&x4[base + lane + 32 * q]);
    }
#pragma unroll
    for (int j = 0; j < 2; ++j) {
        float s = 0.f, ss = 0.f;
#pragma unroll
        for (int q = 0; q < 4; ++q) {
            float4 t = v[j][q];
            s  += (t.x + t.y) + (t.z + t.w);
            ss += (t.x * t.x + t.y * t.y) + (t.z * t.z + t.w * t.w);
        }
#pragma unroll
        for (int o = 16; o; o >>= 1) {
            s  += __shfl_xor_sync(0xffffffffu, s,  o);
            ss += __shfl_xor_sync(0xffffffffu, ss, o);
        }
        if (lane == 0) { sh_rs[row0 + j] = s; sh_rss[row0 + j] = ss; }
    }
    __syncthreads();

    // ---- Aggregate publish (fast path) + in-tile scan + lookback (warp 0) ----
    if (warp == 0) {
        // Warp-parallel aggregate over 16 row sums -> publish immediately so
        // successors unblock before our serial scan finishes.
        double ls  = (lane < TILE_K) ? (double)sh_rs[lane]  : 0.0;
        double lss = (lane < TILE_K) ? (double)sh_rss[lane] : 0.0;
#pragma unroll
        for (int o = 16; o; o >>= 1) {
            ls  += __shfl_xor_sync(0xffffffffu, ls,  o);
            lss += __shfl_xor_sync(0xffffffffu, lss, o);
        }
        const double agg_s = ls, agg_ss = lss;
        if (lane == 0) {
            if (c == 0) {
                g_inc_s[idx]  = agg_s;
                g_inc_ss[idx] = agg_ss;
                __threadfence();
                atomicExch(&g_flag[idx], 2);
            } else {
                g_agg_s[idx]  = agg_s;
                g_agg_ss[idx] = agg_ss;
                __threadfence();
                atomicExch(&g_flag[idx], 1);
            }
            // Serial in-tile inclusive scan (16 rows, fp64) while lookback
            // state propagates through L2.
            double rs = 0.0, rss = 0.0;
#pragma unroll
            for (int r = 0; r < TILE_K; ++r) {
                rs  += (double)sh_rs[r];
                rss += (double)sh_rss[r];
                sh_is[r]  = rs;
                sh_iss[r] = rss;
            }
        }
        __syncwarp();

        double ex_s = 0.0, ex_ss = 0.0;
        if (c != 0) {
            int cur = idx - 1;           // warp-parallel lookback, 32 preds/round
            for (;;) {
                const int p = cur - lane;
                int f = 3;               // sentinel: out of this batch's range
                if (p >= batch_start) {
                    const volatile int* fp = (const volatile int*)&g_flag[p];
                    f = *fp;
                    while (f == 0) { __nanosleep(64); f = *fp; }
                }
                __threadfence();         // acquire: order value reads after flag read
                double vs = 0.0, vss = 0.0;
                const unsigned done_mask = __ballot_sync(0xffffffffu, f >= 2);
                const int L = done_mask ? (__ffs(done_mask) - 1) : 32;
                if (lane < L)                 { vs = g_agg_s[p]; vss = g_agg_ss[p]; }
                else if (lane == L && f == 2) { vs = g_inc_s[p]; vss = g_inc_ss[p]; }
                // lane==L && f==3 (out-of-range sentinel) contributes 0
#pragma unroll
                for (int o = 16; o; o >>= 1) {
                    vs  += __shfl_xor_sync(0xffffffffu, vs,  o);
                    vss += __shfl_xor_sync(0xffffffffu, vss, o);
                }
                ex_s += vs; ex_ss += vss;
                if (done_mask) break;
                cur -= 32;
            }
            if (lane == 0) {
                g_inc_s[idx]  = ex_s + agg_s;
                g_inc_ss[idx] = ex_ss + agg_ss;
                __threadfence();
                atomicExch(&g_flag[idx], 2);
            }
        }
        if (lane == 0) { sh_ex[0] = ex_s; sh_ex[1] = ex_ss; }
    }
    __syncthreads();

    // ---- Per-row mean / inv_std ----
    if (tid < TILE_K) {
        const double ts  = sh_ex[0] + sh_is[tid];
        const double tss = sh_ex[1] + sh_iss[tid];
        const double cnt = (double)((long long)(c * TILE_K + tid + 1) * Hh);
        const double mean = ts / cnt;
        const double var  = tss / cnt - mean * mean;
        sh_mean[tid] = (float)mean;
        sh_istd[tid] = rsqrtf((float)var + 1e-8f);
    }
    __syncthreads();

    // ---- Normalize from registers and store (streaming, write-once) ----
#pragma unroll
    for (int j = 0; j < 2; ++j) {
        const float mean = sh_mean[row0 + j];
        const float istd = sh_istd[row0 + j];
        const int base = (grow0 + row0 + j) * H4;
#pragma unroll
        for (int q = 0; q < 4; ++q) {
            const int col = lane + 32 * q;
            const float4 g = sh_g[col];
            const float4 be = sh_b[col];
            const float4 t = v[j][q];
            float4 o;
            o.x = g.x * (t.x - mean) * istd + be.x;
            o.y = g.y * (t.y - mean) * istd + be.y;
            o.z = g.z * (t.z - mean) * istd + be.z;
            o.w = g.w * (t.w - mean) * istd + be.w;
            __stcs(&out4[base + col], o);
        }
    }
}

extern "C" void kernel_launch(void* const* d_in, const int* in_sizes, int n_in,
                              void* d_out, int out_size)
{
    const float4* x4   = (const float4*)d_in[0];  // inputs (B,K,H) fp32
    const float4* gam4 = (const float4*)d_in[1];  // gamma (1,H)
    const float4* bet4 = (const float4*)d_in[2];  // beta  (1,H)
    float4* out4 = (float4*)d_out;

    k_init_flags<<<(NBLK + 255) / 256, 256>>>();
    k_cumln<<<NBLK, NTHR>>>(x4, gam4, bet4, out4);
}